// round 2
// baseline (speedup 1.0000x reference)
#include <cuda_runtime.h>

#define NND 32768
#define NE  491520
#define FIN 11
#define HD  64
#define NG  2048
#define NPG 16
#define NR  1024
#define NL  4
#define EINC 129
#define NINC 139
#define TE  256          // edges per tile in k_edge

typedef unsigned long long u64;

// ---------------- scratch (device globals; no allocation) ----------------
__device__ float g_h[NND * HD];
__device__ float g_h2[NND * HD];
__device__ float g_PA[NND * HD];
__device__ float g_PB[NND * HD];
__device__ float g_agg[NND * HD];
__device__ float g_radial[NE];
__device__ int   g_perm[NE];
__device__ int   g_count[NND];
__device__ int   g_cursor[NND];

__device__ __forceinline__ float silu(float x) {
    return x / (1.0f + __expf(-x));
}

// ---- packed f32x2 helpers (sm_103a) ----
__device__ __forceinline__ u64 ffma2(u64 a, u64 b, u64 c) {
    u64 d;
    asm("fma.rn.f32x2 %0, %1, %2, %3;" : "=l"(d) : "l"(a), "l"(b), "l"(c));
    return d;
}
__device__ __forceinline__ u64 packdup(float x) {
    u64 d;
    unsigned int r = __float_as_uint(x);
    asm("mov.b64 %0, {%1, %2};" : "=l"(d) : "r"(r), "r"(r));
    return d;
}
__device__ __forceinline__ float2 unpk(u64 v) {
    float2 r;
    asm("mov.b64 {%0, %1}, %2;" : "=f"(r.x), "=f"(r.y) : "l"(v));
    return r;
}

// ---------------- embedding: h = h0 @ emb_w + emb_b ----------------
__global__ void k_embed(const float* __restrict__ h0,
                        const float* __restrict__ emb_w,
                        const float* __restrict__ emb_b) {
    int idx = blockIdx.x * blockDim.x + threadIdx.x;
    int n = idx >> 6, j = idx & 63;
    float acc = emb_b[j];
#pragma unroll
    for (int f = 0; f < FIN; f++)
        acc += h0[n * FIN + f] * emb_w[f * HD + j];
    g_h[idx] = acc;
}

// ---------------- radial per edge ----------------
__global__ void k_radial(const int* __restrict__ edges,
                         const float* __restrict__ pos) {
    int e = blockIdx.x * blockDim.x + threadIdx.x;
    if (e >= NE) return;
    int r = edges[e], c = edges[NE + e];
    float dx = pos[r * 3 + 0] - pos[c * 3 + 0];
    float dy = pos[r * 3 + 1] - pos[c * 3 + 1];
    float dz = pos[r * 3 + 2] - pos[c * 3 + 2];
    g_radial[e] = dx * dx + dy * dy + dz * dz;
}

// ---------------- counting sort of edges by row ----------------
__global__ void k_zero_cnt() {
    g_count[blockIdx.x * blockDim.x + threadIdx.x] = 0;
}
__global__ void k_hist(const int* __restrict__ edges) {
    int e = blockIdx.x * blockDim.x + threadIdx.x;
    if (e < NE) atomicAdd(&g_count[edges[e]], 1);
}
__global__ void k_scan() {
    __shared__ int s[1024];
    int t = threadIdx.x;
    int base = t * 32;
    int loc[32];
    int sum = 0;
#pragma unroll
    for (int i = 0; i < 32; i++) {
        loc[i] = sum;
        sum += g_count[base + i];
    }
    s[t] = sum;
    __syncthreads();
    for (int off = 1; off < 1024; off <<= 1) {
        int v = (t >= off) ? s[t - off] : 0;
        __syncthreads();
        s[t] += v;
        __syncthreads();
    }
    int excl = s[t] - sum;
#pragma unroll
    for (int i = 0; i < 32; i++)
        g_cursor[base + i] = excl + loc[i];
}
__global__ void k_scatter(const int* __restrict__ edges) {
    int e = blockIdx.x * blockDim.x + threadIdx.x;
    if (e >= NE) return;
    int r = edges[e];
    int p = atomicAdd(&g_cursor[r], 1);
    g_perm[p] = e;
}

// ---------------- per-layer precompute: PA = h@W1a + b1, PB = h@W1b; zero agg ----------------
__global__ void k_precomp(const float* __restrict__ h,
                          const float* __restrict__ W1,
                          const float* __restrict__ b1) {
    __shared__ float sA[64 * 64];
    __shared__ float sB[64 * 64];
    int tid = threadIdx.x;
    for (int idx = tid; idx < 4096; idx += blockDim.x) {
        int k = idx >> 6, j = idx & 63;
        int si = k * 64 + ((j & 31) << 1) + (j >> 5);
        sA[si] = W1[k * HD + j];
        sB[si] = W1[(64 + k) * HD + j];
    }
    __syncthreads();
    int lane = tid & 31, wid = tid >> 5;
    int nwarp = (blockDim.x >> 5) * gridDim.x;
    const float2* A2 = (const float2*)sA;
    const float2* B2 = (const float2*)sB;
    for (int n = blockIdx.x * (blockDim.x >> 5) + wid; n < NND; n += nwarp) {
        float hl = h[n * HD + lane];
        float hh = h[n * HD + 32 + lane];
        float a0 = b1[lane], a1 = b1[32 + lane];
        float p0 = 0.f, p1 = 0.f;
#pragma unroll
        for (int k = 0; k < 32; k++) {
            float v = __shfl_sync(0xffffffffu, hl, k);
            float2 wa = A2[k * 32 + lane];
            float2 wb = B2[k * 32 + lane];
            a0 += v * wa.x; a1 += v * wa.y;
            p0 += v * wb.x; p1 += v * wb.y;
        }
#pragma unroll
        for (int k = 0; k < 32; k++) {
            float v = __shfl_sync(0xffffffffu, hh, k);
            float2 wa = A2[(32 + k) * 32 + lane];
            float2 wb = B2[(32 + k) * 32 + lane];
            a0 += v * wa.x; a1 += v * wa.y;
            p0 += v * wb.x; p1 += v * wb.y;
        }
        g_PA[n * HD + lane] = a0;  g_PA[n * HD + 32 + lane] = a1;
        g_PB[n * HD + lane] = p0;  g_PB[n * HD + 32 + lane] = p1;
        g_agg[n * HD + lane] = 0.f; g_agg[n * HD + 32 + lane] = 0.f;
    }
}

// ---------------- edge kernel: tiled f32x2 GEMM over sorted edges ----------------
// smem layout (floats):
//   sW   [64*128]   W2 duplicated along j: sW[k*128+2j]=sW[k*128+2j+1]=W2[k][j]
//   sVT  [64*260]   v transposed: sVT[k*260 + e]
//   sC   [64]       w1c (radial coeff row)
//   sB   [64]       b2
//   sR   [256] int  row index per tile edge
//   sM   [256]      edge mask per tile edge
#define EDGE_SMEM_WORDS (64 * 128 + 64 * 260 + 64 + 64 + 256 + 256)

__global__ __launch_bounds__(256, 2)
void k_edge(const int* __restrict__ edges,
            const float* __restrict__ emask,
            const float* __restrict__ W2,
            const float* __restrict__ b2,
            const float* __restrict__ w1c) {
    extern __shared__ float sm[];
    float* sW  = sm;
    float* sVT = sm + 64 * 128;
    float* sC  = sVT + 64 * 260;
    float* sB  = sC + 64;
    int*   sR  = (int*)(sB + 64);
    float* sM  = (float*)(sR + 256);

    int tid = threadIdx.x;
    // cooperative loads
    for (int idx = tid; idx < 4096; idx += 256) {
        int k = idx >> 6, j = idx & 63;
        float w = W2[k * HD + j];
        sW[k * 128 + 2 * j]     = w;
        sW[k * 128 + 2 * j + 1] = w;
    }
    if (tid < 64) { sC[tid] = w1c[tid]; sB[tid] = b2[tid]; }
    __syncthreads();

    int lane = tid & 31, wid = tid >> 5;
    int tileBase = blockIdx.x * TE;

    // ---- phase 1: compute v for 256 edges (warp handles 32 edges) ----
#pragma unroll 4
    for (int i = 0; i < 32; i++) {
        int el = wid * 32 + i;
        int pe = g_perm[tileBase + el];
        int r = edges[pe], c = edges[NE + pe];
        float rad = g_radial[pe];
        float v0 = silu(g_PA[r * HD + lane] + g_PB[c * HD + lane] + rad * sC[lane]);
        float v1 = silu(g_PA[r * HD + 32 + lane] + g_PB[c * HD + 32 + lane] + rad * sC[32 + lane]);
        sVT[lane * 260 + el]        = v0;
        sVT[(lane + 32) * 260 + el] = v1;
        if (lane == 0) { sR[el] = r; sM[el] = emask[pe]; }
    }
    __syncthreads();

    // ---- phase 2: GEMM  u[e][j] = b2[j] + sum_k v[e][k] * W2[k][j] ----
    // thread: ge = tid>>3 (8 edges), gj = tid&7 (8 j)
    int ge = tid >> 3, gj = tid & 7;
    int eb = ge * 8, jb = gj * 8;

    u64 acc[4][8];
#pragma unroll
    for (int jj = 0; jj < 8; jj++) {
        u64 bini = packdup(sB[jb + jj]);
#pragma unroll
        for (int q = 0; q < 4; q++) acc[q][jj] = bini;
    }

    union U16 { float4 f; u64 u[2]; };

#pragma unroll 8
    for (int k = 0; k < 64; k++) {
        U16 a0, a1;
        a0.f = *(const float4*)(sVT + k * 260 + eb);
        a1.f = *(const float4*)(sVT + k * 260 + eb + 4);
        u64 A[4] = {a0.u[0], a0.u[1], a1.u[0], a1.u[1]};
        U16 b0, b1, b2v, b3;
        const float4* bp = (const float4*)(sW + k * 128 + 2 * jb);
        b0.f = bp[0]; b1.f = bp[1]; b2v.f = bp[2]; b3.f = bp[3];
        u64 B[8] = {b0.u[0], b0.u[1], b1.u[0], b1.u[1],
                    b2v.u[0], b2v.u[1], b3.u[0], b3.u[1]};
#pragma unroll
        for (int q = 0; q < 4; q++)
#pragma unroll
            for (int jj = 0; jj < 8; jj++)
                acc[q][jj] = ffma2(A[q], B[jj], acc[q][jj]);
    }

    // ---- phase 3: silu, mask, run-length reduced atomics (edges sorted by r) ----
    float run[8];
#pragma unroll
    for (int jj = 0; jj < 8; jj++) run[jj] = 0.f;
    int curR = sR[eb];
#pragma unroll
    for (int q = 0; q < 4; q++) {
#pragma unroll
        for (int hh = 0; hh < 2; hh++) {
            int el = eb + 2 * q + hh;
            int r = sR[el];
            float m = sM[el];
            if (r != curR) {
#pragma unroll
                for (int jj = 0; jj < 8; jj++) {
                    atomicAdd(&g_agg[curR * HD + jb + jj], run[jj]);
                    run[jj] = 0.f;
                }
                curR = r;
            }
#pragma unroll
            for (int jj = 0; jj < 8; jj++) {
                float2 p = unpk(acc[q][jj]);
                float val = hh ? p.y : p.x;
                run[jj] += silu(val) * m;
            }
        }
    }
#pragma unroll
    for (int jj = 0; jj < 8; jj++)
        atomicAdd(&g_agg[curR * HD + jb + jj], run[jj]);
}

// ---------------- node kernel: h' = silu([h,agg,h0]@W1 + b1) @ W2 + b2 ----------------
#define NODE_SMEM_FLOATS (4096 * 3 + 11 * 64 + 64 + 64)
__global__ void k_node(const float* __restrict__ h,
                       const float* __restrict__ h0in,
                       const float* __restrict__ W1,
                       const float* __restrict__ b1,
                       const float* __restrict__ W2,
                       const float* __restrict__ b2,
                       float* __restrict__ hout) {
    extern __shared__ float sm[];
    float* sH  = sm;
    float* sAg = sm + 4096;
    float* sF  = sm + 8192;
    float* sW2 = sm + 8192 + 704;
    float* sB1 = sW2 + 4096;
    float* sB2 = sB1 + 64;
    int tid = threadIdx.x;
    for (int idx = tid; idx < 4096; idx += blockDim.x) {
        int k = idx >> 6, j = idx & 63;
        int si = k * 64 + ((j & 31) << 1) + (j >> 5);
        sH[si]  = W1[k * HD + j];
        sAg[si] = W1[(64 + k) * HD + j];
        sW2[si] = W2[k * HD + j];
    }
    for (int idx = tid; idx < FIN * 64; idx += blockDim.x) {
        int k = idx >> 6, j = idx & 63;
        sF[k * 64 + ((j & 31) << 1) + (j >> 5)] = W1[(128 + k) * HD + j];
    }
    if (tid < 64) { sB1[tid] = b1[tid]; sB2[tid] = b2[tid]; }
    __syncthreads();
    int lane = tid & 31, wid = tid >> 5;
    int nwarp = (blockDim.x >> 5) * gridDim.x;
    const float2* H2 = (const float2*)sH;
    const float2* A2 = (const float2*)sAg;
    const float2* F2 = (const float2*)sF;
    const float2* W22 = (const float2*)sW2;
    for (int n = blockIdx.x * (blockDim.x >> 5) + wid; n < NND; n += nwarp) {
        float hl = h[n * HD + lane],      hh = h[n * HD + 32 + lane];
        float al = g_agg[n * HD + lane],  ah = g_agg[n * HD + 32 + lane];
        float t0 = sB1[lane], t1 = sB1[32 + lane];
#pragma unroll
        for (int k = 0; k < 32; k++) {
            float v = __shfl_sync(0xffffffffu, hl, k);
            float2 w = H2[k * 32 + lane];
            t0 += v * w.x; t1 += v * w.y;
            float u = __shfl_sync(0xffffffffu, al, k);
            float2 w2 = A2[k * 32 + lane];
            t0 += u * w2.x; t1 += u * w2.y;
        }
#pragma unroll
        for (int k = 0; k < 32; k++) {
            float v = __shfl_sync(0xffffffffu, hh, k);
            float2 w = H2[(32 + k) * 32 + lane];
            t0 += v * w.x; t1 += v * w.y;
            float u = __shfl_sync(0xffffffffu, ah, k);
            float2 w2 = A2[(32 + k) * 32 + lane];
            t0 += u * w2.x; t1 += u * w2.y;
        }
#pragma unroll
        for (int f = 0; f < FIN; f++) {
            float v = h0in[n * FIN + f];
            float2 w = F2[f * 32 + lane];
            t0 += v * w.x; t1 += v * w.y;
        }
        t0 = silu(t0); t1 = silu(t1);
        float o0 = sB2[lane], o1 = sB2[32 + lane];
#pragma unroll
        for (int k = 0; k < 32; k++) {
            float v = __shfl_sync(0xffffffffu, t0, k);
            float2 w = W22[k * 32 + lane];
            o0 += v * w.x; o1 += v * w.y;
        }
#pragma unroll
        for (int k = 0; k < 32; k++) {
            float v = __shfl_sync(0xffffffffu, t1, k);
            float2 w = W22[(32 + k) * 32 + lane];
            o0 += v * w.x; o1 += v * w.y;
        }
        hout[n * HD + lane] = o0;
        hout[n * HD + 32 + lane] = o1;
    }
}

// ---------------- zero output ----------------
__global__ void k_zero(float* __restrict__ pred) {
    pred[blockIdx.x * blockDim.x + threadIdx.x] = 0.f;
}

// ---------------- final: decoder + pool + graph decoder + signed scatter ----------------
#define FINAL_SMEM_FLOATS (4096 * 3 + 64 * 3 + 256)
__global__ void k_final(const float* __restrict__ h,
                        const float* __restrict__ nmask,
                        const float* __restrict__ dw1, const float* __restrict__ db1,
                        const float* __restrict__ dw2, const float* __restrict__ db2,
                        const float* __restrict__ gw1, const float* __restrict__ gb1,
                        const float* __restrict__ gw2, const float* __restrict__ gb2,
                        const int* __restrict__ ridx, const float* __restrict__ rsign,
                        float* __restrict__ pred) {
    extern __shared__ float sm[];
    float* sD1 = sm;
    float* sD2 = sm + 4096;
    float* sG1 = sm + 8192;
    float* sDB1 = sm + 12288;
    float* sDB2 = sDB1 + 64;
    float* sGB1 = sDB2 + 64;
    float* red  = sGB1 + 64;
    int tid = threadIdx.x;
    for (int idx = tid; idx < 4096; idx += blockDim.x) {
        int k = idx >> 6, j = idx & 63;
        int si = k * 64 + ((j & 31) << 1) + (j >> 5);
        sD1[si] = dw1[k * HD + j];
        sD2[si] = dw2[k * HD + j];
        sG1[si] = gw1[k * HD + j];
    }
    if (tid < 64) { sDB1[tid] = db1[tid]; sDB2[tid] = db2[tid]; sGB1[tid] = gb1[tid]; }
    __syncthreads();
    int lane = tid & 31, wid = tid >> 5;
    int g = blockIdx.x;
    const float2* D1 = (const float2*)sD1;
    const float2* D2 = (const float2*)sD2;
    const float2* G1 = (const float2*)sG1;
    float acc0 = 0.f, acc1 = 0.f;
#pragma unroll
    for (int i = 0; i < 4; i++) {
        int n = g * NPG + wid * 4 + i;
        float hl = h[n * HD + lane], hh = h[n * HD + 32 + lane];
        float t0 = sDB1[lane], t1 = sDB1[32 + lane];
#pragma unroll
        for (int k = 0; k < 32; k++) {
            float v = __shfl_sync(0xffffffffu, hl, k);
            float2 w = D1[k * 32 + lane];
            t0 += v * w.x; t1 += v * w.y;
        }
#pragma unroll
        for (int k = 0; k < 32; k++) {
            float v = __shfl_sync(0xffffffffu, hh, k);
            float2 w = D1[(32 + k) * 32 + lane];
            t0 += v * w.x; t1 += v * w.y;
        }
        t0 = silu(t0); t1 = silu(t1);
        float o0 = sDB2[lane], o1 = sDB2[32 + lane];
#pragma unroll
        for (int k = 0; k < 32; k++) {
            float v = __shfl_sync(0xffffffffu, t0, k);
            float2 w = D2[k * 32 + lane];
            o0 += v * w.x; o1 += v * w.y;
        }
#pragma unroll
        for (int k = 0; k < 32; k++) {
            float v = __shfl_sync(0xffffffffu, t1, k);
            float2 w = D2[(32 + k) * 32 + lane];
            o0 += v * w.x; o1 += v * w.y;
        }
        float m = nmask[n];
        acc0 += o0 * m; acc1 += o1 * m;
    }
    red[wid * 64 + lane] = acc0;
    red[wid * 64 + 32 + lane] = acc1;
    __syncthreads();
    if (wid == 0) {
        float hg0 = red[lane] + red[64 + lane] + red[128 + lane] + red[192 + lane];
        float hg1 = red[32 + lane] + red[96 + lane] + red[160 + lane] + red[224 + lane];
        float t0 = sGB1[lane], t1 = sGB1[32 + lane];
#pragma unroll
        for (int k = 0; k < 32; k++) {
            float v = __shfl_sync(0xffffffffu, hg0, k);
            float2 w = G1[k * 32 + lane];
            t0 += v * w.x; t1 += v * w.y;
        }
#pragma unroll
        for (int k = 0; k < 32; k++) {
            float v = __shfl_sync(0xffffffffu, hg1, k);
            float2 w = G1[(32 + k) * 32 + lane];
            t0 += v * w.x; t1 += v * w.y;
        }
        t0 = silu(t0); t1 = silu(t1);
        float part = t0 * gw2[lane] + t1 * gw2[32 + lane];
#pragma unroll
        for (int off = 16; off > 0; off >>= 1)
            part += __shfl_xor_sync(0xffffffffu, part, off);
        if (lane == 0) {
            float val = (part + gb2[0]) * rsign[g];
            atomicAdd(&pred[ridx[g]], val);
        }
    }
}

// ---------------- launch ----------------
extern "C" void kernel_launch(void* const* d_in, const int* in_sizes, int n_in,
                              void* d_out, int out_size) {
    const float* h0    = (const float*)d_in[0];
    const float* pos   = (const float*)d_in[1];
    const int*   edges = (const int*)  d_in[2];
    const float* nmask = (const float*)d_in[3];
    const float* emask = (const float*)d_in[4];
    const int*   ridx  = (const int*)  d_in[5];
    const float* rsign = (const float*)d_in[6];
    const float* emb_w = (const float*)d_in[7];
    const float* emb_b = (const float*)d_in[8];
    const float* ew1   = (const float*)d_in[9];
    const float* eb1   = (const float*)d_in[10];
    const float* ew2   = (const float*)d_in[11];
    const float* eb2   = (const float*)d_in[12];
    const float* nw1   = (const float*)d_in[13];
    const float* nb1   = (const float*)d_in[14];
    const float* nw2   = (const float*)d_in[15];
    const float* nb2   = (const float*)d_in[16];
    const float* dw1   = (const float*)d_in[17];
    const float* db1   = (const float*)d_in[18];
    const float* dw2   = (const float*)d_in[19];
    const float* db2   = (const float*)d_in[20];
    const float* gw1   = (const float*)d_in[21];
    const float* gb1   = (const float*)d_in[22];
    const float* gw2   = (const float*)d_in[23];
    const float* gb2   = (const float*)d_in[24];
    float* pred = (float*)d_out;

    float *hA, *hB;
    cudaGetSymbolAddress((void**)&hA, g_h);
    cudaGetSymbolAddress((void**)&hB, g_h2);

    cudaFuncSetAttribute(k_node, cudaFuncAttributeMaxDynamicSharedMemorySize,
                         NODE_SMEM_FLOATS * 4);
    cudaFuncSetAttribute(k_final, cudaFuncAttributeMaxDynamicSharedMemorySize,
                         FINAL_SMEM_FLOATS * 4);
    cudaFuncSetAttribute(k_edge, cudaFuncAttributeMaxDynamicSharedMemorySize,
                         EDGE_SMEM_WORDS * 4);

    k_embed<<<NND * HD / 256, 256>>>(h0, emb_w, emb_b);
    k_radial<<<(NE + 255) / 256, 256>>>(edges, pos);

    // counting sort of edges by source node (once; reused by all layers)
    k_zero_cnt<<<NND / 256, 256>>>();
    k_hist<<<(NE + 255) / 256, 256>>>(edges);
    k_scan<<<1, 1024>>>();
    k_scatter<<<(NE + 255) / 256, 256>>>(edges);

    float* hc = hA;
    float* hn = hB;
    for (int l = 0; l < NL; l++) {
        k_precomp<<<1024, 256>>>(hc, ew1 + l * EINC * HD, eb1 + l * HD);
        k_edge<<<NE / TE, 256, EDGE_SMEM_WORDS * 4>>>(
            edges, emask, ew2 + l * HD * HD, eb2 + l * HD,
            ew1 + l * EINC * HD + 128 * HD);
        k_node<<<1024, 256, NODE_SMEM_FLOATS * 4>>>(
            hc, h0, nw1 + l * NINC * HD, nb1 + l * HD,
            nw2 + l * HD * HD, nb2 + l * HD, hn);
        float* t = hc; hc = hn; hn = t;
    }

    k_zero<<<NR / 256, 256>>>(pred);
    k_final<<<NG, 128, FINAL_SMEM_FLOATS * 4>>>(
        hc, nmask, dw1, db1, dw2, db2, gw1, gb1, gw2, gb2, ridx, rsign, pred);
}

// round 3
// speedup vs baseline: 1.6298x; 1.6298x over previous
#include <cuda_runtime.h>

#define NND 32768
#define NE  491520
#define FIN 11
#define HD  64
#define NG  2048
#define NPG 16
#define NR  1024
#define NL  4
#define EINC 129
#define NINC 139
#define TE  128          // edges per tile in k_edge
#define SV  65           // sV row stride (odd -> conflict-free)

typedef unsigned long long u64;

// ---------------- scratch (device globals; no allocation) ----------------
__device__ float g_h[NND * HD];
__device__ float g_h2[NND * HD];
__device__ float g_PA[NND * HD];
__device__ float g_PB[NND * HD];
__device__ float g_agg[NND * HD];
__device__ float g_radial[NE];
__device__ int   g_perm[NE];
__device__ int   g_count[NND];
__device__ int   g_cursor[NND];

__device__ __forceinline__ float silu(float x) {
    return x / (1.0f + __expf(-x));
}

// ---- packed f32x2 helpers (sm_103a) ----
__device__ __forceinline__ u64 ffma2(u64 a, u64 b, u64 c) {
    u64 d;
    asm("fma.rn.f32x2 %0, %1, %2, %3;" : "=l"(d) : "l"(a), "l"(b), "l"(c));
    return d;
}
__device__ __forceinline__ u64 packdup(float x) {
    u64 d;
    unsigned int r = __float_as_uint(x);
    asm("mov.b64 %0, {%1, %2};" : "=l"(d) : "r"(r), "r"(r));
    return d;
}
__device__ __forceinline__ float2 unpk(u64 v) {
    float2 r;
    asm("mov.b64 {%0, %1}, %2;" : "=f"(r.x), "=f"(r.y) : "l"(v));
    return r;
}

// ---------------- embedding ----------------
__global__ void k_embed(const float* __restrict__ h0,
                        const float* __restrict__ emb_w,
                        const float* __restrict__ emb_b) {
    int idx = blockIdx.x * blockDim.x + threadIdx.x;
    int n = idx >> 6, j = idx & 63;
    float acc = emb_b[j];
#pragma unroll
    for (int f = 0; f < FIN; f++)
        acc += h0[n * FIN + f] * emb_w[f * HD + j];
    g_h[idx] = acc;
}

// ---------------- radial per edge ----------------
__global__ void k_radial(const int* __restrict__ edges,
                         const float* __restrict__ pos) {
    int e = blockIdx.x * blockDim.x + threadIdx.x;
    if (e >= NE) return;
    int r = edges[e], c = edges[NE + e];
    float dx = pos[r * 3 + 0] - pos[c * 3 + 0];
    float dy = pos[r * 3 + 1] - pos[c * 3 + 1];
    float dz = pos[r * 3 + 2] - pos[c * 3 + 2];
    g_radial[e] = dx * dx + dy * dy + dz * dz;
}

// ---------------- counting sort of edges by row ----------------
__global__ void k_zero_cnt() {
    g_count[blockIdx.x * blockDim.x + threadIdx.x] = 0;
}
__global__ void k_hist(const int* __restrict__ edges) {
    int e = blockIdx.x * blockDim.x + threadIdx.x;
    if (e < NE) atomicAdd(&g_count[edges[e]], 1);
}
__global__ void k_scan() {
    __shared__ int s[1024];
    int t = threadIdx.x;
    int base = t * 32;
    int loc[32];
    int sum = 0;
#pragma unroll
    for (int i = 0; i < 32; i++) {
        loc[i] = sum;
        sum += g_count[base + i];
    }
    s[t] = sum;
    __syncthreads();
    for (int off = 1; off < 1024; off <<= 1) {
        int v = (t >= off) ? s[t - off] : 0;
        __syncthreads();
        s[t] += v;
        __syncthreads();
    }
    int excl = s[t] - sum;
#pragma unroll
    for (int i = 0; i < 32; i++)
        g_cursor[base + i] = excl + loc[i];
}
__global__ void k_scatter(const int* __restrict__ edges) {
    int e = blockIdx.x * blockDim.x + threadIdx.x;
    if (e >= NE) return;
    int r = edges[e];
    int p = atomicAdd(&g_cursor[r], 1);
    g_perm[p] = e;
}

// ---------------- per-layer precompute: PA = h@W1a + b1, PB = h@W1b; zero agg ----------------
__global__ void k_precomp(const float* __restrict__ h,
                          const float* __restrict__ W1,
                          const float* __restrict__ b1) {
    __shared__ float sA[64 * 64];
    __shared__ float sB[64 * 64];
    int tid = threadIdx.x;
    for (int idx = tid; idx < 4096; idx += blockDim.x) {
        int k = idx >> 6, j = idx & 63;
        int si = k * 64 + ((j & 31) << 1) + (j >> 5);
        sA[si] = W1[k * HD + j];
        sB[si] = W1[(64 + k) * HD + j];
    }
    __syncthreads();
    int lane = tid & 31, wid = tid >> 5;
    int nwarp = (blockDim.x >> 5) * gridDim.x;
    const float2* A2 = (const float2*)sA;
    const float2* B2 = (const float2*)sB;
    for (int n = blockIdx.x * (blockDim.x >> 5) + wid; n < NND; n += nwarp) {
        float hl = h[n * HD + lane];
        float hh = h[n * HD + 32 + lane];
        float a0 = b1[lane], a1 = b1[32 + lane];
        float p0 = 0.f, p1 = 0.f;
#pragma unroll
        for (int k = 0; k < 32; k++) {
            float v = __shfl_sync(0xffffffffu, hl, k);
            float2 wa = A2[k * 32 + lane];
            float2 wb = B2[k * 32 + lane];
            a0 += v * wa.x; a1 += v * wa.y;
            p0 += v * wb.x; p1 += v * wb.y;
        }
#pragma unroll
        for (int k = 0; k < 32; k++) {
            float v = __shfl_sync(0xffffffffu, hh, k);
            float2 wa = A2[(32 + k) * 32 + lane];
            float2 wb = B2[(32 + k) * 32 + lane];
            a0 += v * wa.x; a1 += v * wa.y;
            p0 += v * wb.x; p1 += v * wb.y;
        }
        g_PA[n * HD + lane] = a0;  g_PA[n * HD + 32 + lane] = a1;
        g_PB[n * HD + lane] = p0;  g_PB[n * HD + 32 + lane] = p1;
        g_agg[n * HD + lane] = 0.f; g_agg[n * HD + 32 + lane] = 0.f;
    }
}

// ---------------- edge kernel: e-major SMEM GEMM, f32x2 packed over j ----------------
// smem (floats): sW[64*64], sV[TE*SV], sC[64], sB[64], sR[TE] int, sM[TE]
#define EDGE_SMEM_WORDS (64 * 64 + TE * SV + 64 + 64 + TE + TE)

__global__ __launch_bounds__(256)
void k_edge(const int* __restrict__ edges,
            const float* __restrict__ emask,
            const float* __restrict__ W2,
            const float* __restrict__ b2,
            const float* __restrict__ w1c) {
    extern __shared__ float sm[];
    float* sW = sm;                       // [64][64] row-major (k, j)
    float* sV = sm + 4096;                // [TE][SV]
    float* sC = sV + TE * SV;
    float* sB = sC + 64;
    int*   sR = (int*)(sB + 64);
    float* sM = (float*)(sR + TE);

    int tid = threadIdx.x;
    {
        const float4* src = (const float4*)W2;
        float4* dst = (float4*)sW;
#pragma unroll
        for (int i = 0; i < 4; i++)
            dst[tid + 256 * i] = src[tid + 256 * i];
    }
    if (tid < 64) { sC[tid] = w1c[tid]; sB[tid] = b2[tid]; }
    __syncthreads();

    int lane = tid & 31, wid = tid >> 5;
    int tileBase = blockIdx.x * TE;
    float c0 = sC[lane], c1 = sC[32 + lane];

    // ---- phase 1: v for 128 edges (16 per warp); coalesced stores ----
#pragma unroll 4
    for (int i = 0; i < 16; i++) {
        int el = wid * 16 + i;
        int pe = g_perm[tileBase + el];
        int r = edges[pe], c = edges[NE + pe];
        float rad = g_radial[pe];
        float v0 = silu(g_PA[r * HD + lane]      + g_PB[c * HD + lane]      + rad * c0);
        float v1 = silu(g_PA[r * HD + 32 + lane] + g_PB[c * HD + 32 + lane] + rad * c1);
        sV[el * SV + lane]      = v0;
        sV[el * SV + 32 + lane] = v1;
        if (lane == 0) { sR[el] = r; sM[el] = emask[pe]; }
    }
    __syncthreads();

    // ---- phase 2: u[e][j] = b2[j] + sum_k v[e][k]*W2[k][j], 4e x 8j per thread ----
    int ge = tid >> 3, gj = tid & 7;
    int eb = ge * 4, jb = gj * 8;

    union U16 { float4 f; u64 u[2]; };

    u64 acc[4][4];
    {
        U16 bb0, bb1;
        bb0.f = *(const float4*)(sB + jb);
        bb1.f = *(const float4*)(sB + jb + 4);
#pragma unroll
        for (int q = 0; q < 4; q++) {
            acc[q][0] = bb0.u[0]; acc[q][1] = bb0.u[1];
            acc[q][2] = bb1.u[0]; acc[q][3] = bb1.u[1];
        }
    }

#pragma unroll 4
    for (int k = 0; k < 64; k++) {
        U16 w0, w1;
        const float4* bp = (const float4*)(sW + k * 64 + jb);
        w0.f = bp[0]; w1.f = bp[1];
        u64 B0 = w0.u[0], B1 = w0.u[1], B2v = w1.u[0], B3 = w1.u[1];
#pragma unroll
        for (int q = 0; q < 4; q++) {
            u64 a = packdup(sV[(eb + q) * SV + k]);
            acc[q][0] = ffma2(a, B0,  acc[q][0]);
            acc[q][1] = ffma2(a, B1,  acc[q][1]);
            acc[q][2] = ffma2(a, B2v, acc[q][2]);
            acc[q][3] = ffma2(a, B3,  acc[q][3]);
        }
    }

    // ---- phase 3: silu, mask, run-length reduced vector atomics ----
    float run[8];
#pragma unroll
    for (int jj = 0; jj < 8; jj++) run[jj] = 0.f;
    int curR = sR[eb];
#pragma unroll
    for (int q = 0; q < 4; q++) {
        int r = sR[eb + q];
        float m = sM[eb + q];
        if (r != curR) {
            float4* base = (float4*)&g_agg[curR * HD + jb];
            atomicAdd(base,     make_float4(run[0], run[1], run[2], run[3]));
            atomicAdd(base + 1, make_float4(run[4], run[5], run[6], run[7]));
#pragma unroll
            for (int jj = 0; jj < 8; jj++) run[jj] = 0.f;
            curR = r;
        }
#pragma unroll
        for (int jp = 0; jp < 4; jp++) {
            float2 p = unpk(acc[q][jp]);
            run[2 * jp]     += silu(p.x) * m;
            run[2 * jp + 1] += silu(p.y) * m;
        }
    }
    {
        float4* base = (float4*)&g_agg[curR * HD + jb];
        atomicAdd(base,     make_float4(run[0], run[1], run[2], run[3]));
        atomicAdd(base + 1, make_float4(run[4], run[5], run[6], run[7]));
    }
}

// ---------------- node kernel ----------------
#define NODE_SMEM_FLOATS (4096 * 3 + 11 * 64 + 64 + 64)
__global__ void k_node(const float* __restrict__ h,
                       const float* __restrict__ h0in,
                       const float* __restrict__ W1,
                       const float* __restrict__ b1,
                       const float* __restrict__ W2,
                       const float* __restrict__ b2,
                       float* __restrict__ hout) {
    extern __shared__ float sm[];
    float* sH  = sm;
    float* sAg = sm + 4096;
    float* sF  = sm + 8192;
    float* sW2 = sm + 8192 + 704;
    float* sB1 = sW2 + 4096;
    float* sB2 = sB1 + 64;
    int tid = threadIdx.x;
    for (int idx = tid; idx < 4096; idx += blockDim.x) {
        int k = idx >> 6, j = idx & 63;
        int si = k * 64 + ((j & 31) << 1) + (j >> 5);
        sH[si]  = W1[k * HD + j];
        sAg[si] = W1[(64 + k) * HD + j];
        sW2[si] = W2[k * HD + j];
    }
    for (int idx = tid; idx < FIN * 64; idx += blockDim.x) {
        int k = idx >> 6, j = idx & 63;
        sF[k * 64 + ((j & 31) << 1) + (j >> 5)] = W1[(128 + k) * HD + j];
    }
    if (tid < 64) { sB1[tid] = b1[tid]; sB2[tid] = b2[tid]; }
    __syncthreads();
    int lane = tid & 31, wid = tid >> 5;
    int nwarp = (blockDim.x >> 5) * gridDim.x;
    const float2* H2 = (const float2*)sH;
    const float2* A2 = (const float2*)sAg;
    const float2* F2 = (const float2*)sF;
    const float2* W22 = (const float2*)sW2;
    for (int n = blockIdx.x * (blockDim.x >> 5) + wid; n < NND; n += nwarp) {
        float hl = h[n * HD + lane],      hh = h[n * HD + 32 + lane];
        float al = g_agg[n * HD + lane],  ah = g_agg[n * HD + 32 + lane];
        float t0 = sB1[lane], t1 = sB1[32 + lane];
#pragma unroll
        for (int k = 0; k < 32; k++) {
            float v = __shfl_sync(0xffffffffu, hl, k);
            float2 w = H2[k * 32 + lane];
            t0 += v * w.x; t1 += v * w.y;
            float u = __shfl_sync(0xffffffffu, al, k);
            float2 w2 = A2[k * 32 + lane];
            t0 += u * w2.x; t1 += u * w2.y;
        }
#pragma unroll
        for (int k = 0; k < 32; k++) {
            float v = __shfl_sync(0xffffffffu, hh, k);
            float2 w = H2[(32 + k) * 32 + lane];
            t0 += v * w.x; t1 += v * w.y;
            float u = __shfl_sync(0xffffffffu, ah, k);
            float2 w2 = A2[(32 + k) * 32 + lane];
            t0 += u * w2.x; t1 += u * w2.y;
        }
#pragma unroll
        for (int f = 0; f < FIN; f++) {
            float v = h0in[n * FIN + f];
            float2 w = F2[f * 32 + lane];
            t0 += v * w.x; t1 += v * w.y;
        }
        t0 = silu(t0); t1 = silu(t1);
        float o0 = sB2[lane], o1 = sB2[32 + lane];
#pragma unroll
        for (int k = 0; k < 32; k++) {
            float v = __shfl_sync(0xffffffffu, t0, k);
            float2 w = W22[k * 32 + lane];
            o0 += v * w.x; o1 += v * w.y;
        }
#pragma unroll
        for (int k = 0; k < 32; k++) {
            float v = __shfl_sync(0xffffffffu, t1, k);
            float2 w = W22[(32 + k) * 32 + lane];
            o0 += v * w.x; o1 += v * w.y;
        }
        hout[n * HD + lane] = o0;
        hout[n * HD + 32 + lane] = o1;
    }
}

// ---------------- zero output ----------------
__global__ void k_zero(float* __restrict__ pred) {
    pred[blockIdx.x * blockDim.x + threadIdx.x] = 0.f;
}

// ---------------- final ----------------
#define FINAL_SMEM_FLOATS (4096 * 3 + 64 * 3 + 256)
__global__ void k_final(const float* __restrict__ h,
                        const float* __restrict__ nmask,
                        const float* __restrict__ dw1, const float* __restrict__ db1,
                        const float* __restrict__ dw2, const float* __restrict__ db2,
                        const float* __restrict__ gw1, const float* __restrict__ gb1,
                        const float* __restrict__ gw2, const float* __restrict__ gb2,
                        const int* __restrict__ ridx, const float* __restrict__ rsign,
                        float* __restrict__ pred) {
    extern __shared__ float sm[];
    float* sD1 = sm;
    float* sD2 = sm + 4096;
    float* sG1 = sm + 8192;
    float* sDB1 = sm + 12288;
    float* sDB2 = sDB1 + 64;
    float* sGB1 = sDB2 + 64;
    float* red  = sGB1 + 64;
    int tid = threadIdx.x;
    for (int idx = tid; idx < 4096; idx += blockDim.x) {
        int k = idx >> 6, j = idx & 63;
        int si = k * 64 + ((j & 31) << 1) + (j >> 5);
        sD1[si] = dw1[k * HD + j];
        sD2[si] = dw2[k * HD + j];
        sG1[si] = gw1[k * HD + j];
    }
    if (tid < 64) { sDB1[tid] = db1[tid]; sDB2[tid] = db2[tid]; sGB1[tid] = gb1[tid]; }
    __syncthreads();
    int lane = tid & 31, wid = tid >> 5;
    int g = blockIdx.x;
    const float2* D1 = (const float2*)sD1;
    const float2* D2 = (const float2*)sD2;
    const float2* G1 = (const float2*)sG1;
    float acc0 = 0.f, acc1 = 0.f;
#pragma unroll
    for (int i = 0; i < 4; i++) {
        int n = g * NPG + wid * 4 + i;
        float hl = h[n * HD + lane], hh = h[n * HD + 32 + lane];
        float t0 = sDB1[lane], t1 = sDB1[32 + lane];
#pragma unroll
        for (int k = 0; k < 32; k++) {
            float v = __shfl_sync(0xffffffffu, hl, k);
            float2 w = D1[k * 32 + lane];
            t0 += v * w.x; t1 += v * w.y;
        }
#pragma unroll
        for (int k = 0; k < 32; k++) {
            float v = __shfl_sync(0xffffffffu, hh, k);
            float2 w = D1[(32 + k) * 32 + lane];
            t0 += v * w.x; t1 += v * w.y;
        }
        t0 = silu(t0); t1 = silu(t1);
        float o0 = sDB2[lane], o1 = sDB2[32 + lane];
#pragma unroll
        for (int k = 0; k < 32; k++) {
            float v = __shfl_sync(0xffffffffu, t0, k);
            float2 w = D2[k * 32 + lane];
            o0 += v * w.x; o1 += v * w.y;
        }
#pragma unroll
        for (int k = 0; k < 32; k++) {
            float v = __shfl_sync(0xffffffffu, t1, k);
            float2 w = D2[(32 + k) * 32 + lane];
            o0 += v * w.x; o1 += v * w.y;
        }
        float m = nmask[n];
        acc0 += o0 * m; acc1 += o1 * m;
    }
    red[wid * 64 + lane] = acc0;
    red[wid * 64 + 32 + lane] = acc1;
    __syncthreads();
    if (wid == 0) {
        float hg0 = red[lane] + red[64 + lane] + red[128 + lane] + red[192 + lane];
        float hg1 = red[32 + lane] + red[96 + lane] + red[160 + lane] + red[224 + lane];
        float t0 = sGB1[lane], t1 = sGB1[32 + lane];
#pragma unroll
        for (int k = 0; k < 32; k++) {
            float v = __shfl_sync(0xffffffffu, hg0, k);
            float2 w = G1[k * 32 + lane];
            t0 += v * w.x; t1 += v * w.y;
        }
#pragma unroll
        for (int k = 0; k < 32; k++) {
            float v = __shfl_sync(0xffffffffu, hg1, k);
            float2 w = G1[(32 + k) * 32 + lane];
            t0 += v * w.x; t1 += v * w.y;
        }
        t0 = silu(t0); t1 = silu(t1);
        float part = t0 * gw2[lane] + t1 * gw2[32 + lane];
#pragma unroll
        for (int off = 16; off > 0; off >>= 1)
            part += __shfl_xor_sync(0xffffffffu, part, off);
        if (lane == 0) {
            float val = (part + gb2[0]) * rsign[g];
            atomicAdd(&pred[ridx[g]], val);
        }
    }
}

// ---------------- launch ----------------
extern "C" void kernel_launch(void* const* d_in, const int* in_sizes, int n_in,
                              void* d_out, int out_size) {
    const float* h0    = (const float*)d_in[0];
    const float* pos   = (const float*)d_in[1];
    const int*   edges = (const int*)  d_in[2];
    const float* nmask = (const float*)d_in[3];
    const float* emask = (const float*)d_in[4];
    const int*   ridx  = (const int*)  d_in[5];
    const float* rsign = (const float*)d_in[6];
    const float* emb_w = (const float*)d_in[7];
    const float* emb_b = (const float*)d_in[8];
    const float* ew1   = (const float*)d_in[9];
    const float* eb1   = (const float*)d_in[10];
    const float* ew2   = (const float*)d_in[11];
    const float* eb2   = (const float*)d_in[12];
    const float* nw1   = (const float*)d_in[13];
    const float* nb1   = (const float*)d_in[14];
    const float* nw2   = (const float*)d_in[15];
    const float* nb2   = (const float*)d_in[16];
    const float* dw1   = (const float*)d_in[17];
    const float* db1   = (const float*)d_in[18];
    const float* dw2   = (const float*)d_in[19];
    const float* db2   = (const float*)d_in[20];
    const float* gw1   = (const float*)d_in[21];
    const float* gb1   = (const float*)d_in[22];
    const float* gw2   = (const float*)d_in[23];
    const float* gb2   = (const float*)d_in[24];
    float* pred = (float*)d_out;

    float *hA, *hB;
    cudaGetSymbolAddress((void**)&hA, g_h);
    cudaGetSymbolAddress((void**)&hB, g_h2);

    cudaFuncSetAttribute(k_node, cudaFuncAttributeMaxDynamicSharedMemorySize,
                         NODE_SMEM_FLOATS * 4);
    cudaFuncSetAttribute(k_final, cudaFuncAttributeMaxDynamicSharedMemorySize,
                         FINAL_SMEM_FLOATS * 4);
    cudaFuncSetAttribute(k_edge, cudaFuncAttributeMaxDynamicSharedMemorySize,
                         EDGE_SMEM_WORDS * 4);

    k_embed<<<NND * HD / 256, 256>>>(h0, emb_w, emb_b);
    k_radial<<<(NE + 255) / 256, 256>>>(edges, pos);

    // counting sort of edges by source node
    k_zero_cnt<<<NND / 256, 256>>>();
    k_hist<<<(NE + 255) / 256, 256>>>(edges);
    k_scan<<<1, 1024>>>();
    k_scatter<<<(NE + 255) / 256, 256>>>(edges);

    float* hc = hA;
    float* hn = hB;
    for (int l = 0; l < NL; l++) {
        k_precomp<<<1024, 256>>>(hc, ew1 + l * EINC * HD, eb1 + l * HD);
        k_edge<<<NE / TE, 256, EDGE_SMEM_WORDS * 4>>>(
            edges, emask, ew2 + l * HD * HD, eb2 + l * HD,
            ew1 + l * EINC * HD + 128 * HD);
        k_node<<<1024, 256, NODE_SMEM_FLOATS * 4>>>(
            hc, h0, nw1 + l * NINC * HD, nb1 + l * HD,
            nw2 + l * HD * HD, nb2 + l * HD, hn);
        float* t = hc; hc = hn; hn = t;
    }

    k_zero<<<NR / 256, 256>>>(pred);
    k_final<<<NG, 128, FINAL_SMEM_FLOATS * 4>>>(
        hc, nmask, dw1, db1, dw2, db2, gw1, gb1, gw2, gb2, ridx, rsign, pred);
}

// round 5
// speedup vs baseline: 2.0442x; 1.2543x over previous
#include <cuda_runtime.h>

#define NND 32768
#define NE  491520
#define FIN 11
#define HD  64
#define NG  2048
#define NPG 16
#define NR  1024
#define NL  4
#define EINC 129
#define NINC 139
#define TE  128
#define ST  68   // sT/sH row stride: multiple of 4 for float4 alignment

typedef unsigned long long u64;

// ---------------- scratch (device globals; no allocation) ----------------
__device__ float g_h[NND * HD];
__device__ float g_PA[NND * HD];
__device__ float g_PB[NND * HD];
__device__ float g_agg[NND * HD];
__device__ float g_radial[NE];
__device__ int   g_count[NND];
__device__ int   g_cursor[NND];
__device__ int   g_rowS[NE];
__device__ int   g_colS[NE];
__device__ float g_radS[NE];
__device__ float g_mS[NE];
__device__ float g_FZ[NL * NND * HD];

__device__ __forceinline__ float silu(float x) {
    return x / (1.0f + __expf(-x));
}

// ---- packed f32x2 helpers (sm_103a) ----
__device__ __forceinline__ u64 ffma2(u64 a, u64 b, u64 c) {
    u64 d;
    asm("fma.rn.f32x2 %0, %1, %2, %3;" : "=l"(d) : "l"(a), "l"(b), "l"(c));
    return d;
}
__device__ __forceinline__ u64 packdup(float x) {
    u64 d;
    unsigned int r = __float_as_uint(x);
    asm("mov.b64 %0, {%1, %2};" : "=l"(d) : "r"(r), "r"(r));
    return d;
}
__device__ __forceinline__ float2 unpk(u64 v) {
    float2 r;
    asm("mov.b64 {%0, %1}, %2;" : "=f"(r.x), "=f"(r.y) : "l"(v));
    return r;
}
union U16 { float4 f; u64 u[2]; float s[4]; };

// ---------------- embedding + zero count ----------------
__global__ void k_embed_zero(const float* __restrict__ h0,
                             const float* __restrict__ emb_w,
                             const float* __restrict__ emb_b) {
    int idx = blockIdx.x * blockDim.x + threadIdx.x;
    if (idx < NND) g_count[idx] = 0;
    int n = idx >> 6, j = idx & 63;
    float acc = emb_b[j];
#pragma unroll
    for (int f = 0; f < FIN; f++)
        acc += h0[n * FIN + f] * emb_w[f * HD + j];
    g_h[idx] = acc;
}

// ---------------- radial + histogram ----------------
__global__ void k_radial_hist(const int* __restrict__ edges,
                              const float* __restrict__ pos) {
    int e = blockIdx.x * blockDim.x + threadIdx.x;
    if (e >= NE) return;
    int r = edges[e], c = edges[NE + e];
    float dx = pos[r * 3 + 0] - pos[c * 3 + 0];
    float dy = pos[r * 3 + 1] - pos[c * 3 + 1];
    float dz = pos[r * 3 + 2] - pos[c * 3 + 2];
    g_radial[e] = dx * dx + dy * dy + dz * dz;
    atomicAdd(&g_count[r], 1);
}

// ---------------- scan ----------------
__global__ void k_scan() {
    __shared__ int s[1024];
    int t = threadIdx.x;
    int base = t * 32;
    int loc[32];
    int sum = 0;
#pragma unroll
    for (int i = 0; i < 32; i++) {
        loc[i] = sum;
        sum += g_count[base + i];
    }
    s[t] = sum;
    __syncthreads();
    for (int off = 1; off < 1024; off <<= 1) {
        int v = (t >= off) ? s[t - off] : 0;
        __syncthreads();
        s[t] += v;
        __syncthreads();
    }
    int excl = s[t] - sum;
#pragma unroll
    for (int i = 0; i < 32; i++)
        g_cursor[base + i] = excl + loc[i];
}

// ---------------- scatter + prep sorted arrays ----------------
__global__ void k_scatterprep(const int* __restrict__ edges,
                              const float* __restrict__ emask) {
    int e = blockIdx.x * blockDim.x + threadIdx.x;
    if (e >= NE) return;
    int r = edges[e];
    int p = atomicAdd(&g_cursor[r], 1);
    g_rowS[p] = r;
    g_colS[p] = edges[NE + e];
    g_radS[p] = g_radial[e];
    g_mS[p]   = emask[e];
}

// ---------------- FZ_l = h0 @ nw1[l, 128:139, :] + nb1[l] ----------------
__global__ void k_fz(const float* __restrict__ h0,
                     const float* __restrict__ nw1,
                     const float* __restrict__ nb1) {
    int idx = blockIdx.x * blockDim.x + threadIdx.x;
    int l = idx >> 21;
    int n = (idx >> 6) & (NND - 1);
    int j = idx & 63;
    const float* W = nw1 + l * NINC * HD + 128 * HD;
    float acc = nb1[l * HD + j];
#pragma unroll
    for (int f = 0; f < FIN; f++)
        acc += h0[n * FIN + f] * W[f * HD + j];
    g_FZ[idx] = acc;
}

// ---------------- precomp0: PA/PB for layer 0 ----------------
#define P0_SMEM (64 * 128 + 64 * 65 + 128)
__global__ __launch_bounds__(256)
void k_precomp0(const float* __restrict__ W1,
                const float* __restrict__ b1) {
    extern __shared__ float sm[];
    float* sW = sm;
    float* sX = sm + 8192;
    float* sBp = sX + 64 * 65;
    int tid = threadIdx.x;
    int n0 = blockIdx.x * 64;

    for (int idx = tid; idx < 8192; idx += 256) {
        int k = idx >> 7, j = idx & 127;
        sW[idx] = (j < 64) ? W1[k * HD + j] : W1[(64 + k) * HD + (j - 64)];
    }
    for (int idx = tid; idx < 4096; idx += 256) {
        int n = idx >> 6, c = idx & 63;
        sX[n * 65 + c] = g_h[(n0 + n) * HD + c];
    }
    if (tid < 128) sBp[tid] = (tid < 64) ? b1[tid] : 0.f;
    __syncthreads();

    {
        float4 z = make_float4(0.f, 0.f, 0.f, 0.f);
        float4* a4 = (float4*)&g_agg[n0 * HD];
#pragma unroll
        for (int i = 0; i < 4; i++) a4[tid + 256 * i] = z;
    }

    int gn = tid >> 4, gj = tid & 15;
    int nb = gn * 4, jb = gj * 8;

    u64 acc[4][4];
    {
        U16 b0, b1v;
        b0.f = *(const float4*)(sBp + jb);
        b1v.f = *(const float4*)(sBp + jb + 4);
#pragma unroll
        for (int q = 0; q < 4; q++) {
            acc[q][0] = b0.u[0]; acc[q][1] = b0.u[1];
            acc[q][2] = b1v.u[0]; acc[q][3] = b1v.u[1];
        }
    }
#pragma unroll 4
    for (int k = 0; k < 64; k++) {
        U16 w0, w1;
        const float4* bp = (const float4*)(sW + k * 128 + jb);
        w0.f = bp[0]; w1.f = bp[1];
#pragma unroll
        for (int q = 0; q < 4; q++) {
            u64 a = packdup(sX[(nb + q) * 65 + k]);
            acc[q][0] = ffma2(a, w0.u[0], acc[q][0]);
            acc[q][1] = ffma2(a, w0.u[1], acc[q][1]);
            acc[q][2] = ffma2(a, w1.u[0], acc[q][2]);
            acc[q][3] = ffma2(a, w1.u[1], acc[q][3]);
        }
    }
    float* dst = (gj < 8) ? g_PA : g_PB;
    int col = (gj < 8) ? jb : (jb - 64);
#pragma unroll
    for (int q = 0; q < 4; q++) {
        U16 o0, o1;
        o0.u[0] = acc[q][0]; o0.u[1] = acc[q][1];
        o1.u[0] = acc[q][2]; o1.u[1] = acc[q][3];
        float4* d4 = (float4*)&dst[(n0 + nb + q) * HD + col];
        d4[0] = o0.f; d4[1] = o1.f;
    }
}

// ---------------- edge kernel ----------------
#define EDGE_SMEM (4096 + TE * 65 + 64 + 64 + TE + TE + TE + TE)
__global__ __launch_bounds__(256)
void k_edge(const float* __restrict__ W2,
            const float* __restrict__ b2,
            const float* __restrict__ w1c) {
    extern __shared__ float sm[];
    float* sW  = sm;
    float* sV  = sm + 4096;
    float* sC  = sV + TE * 65;
    float* sB  = sC + 64;
    int*   sR  = (int*)(sB + 64);
    int*   sCl = sR + TE;
    float* sRd = (float*)(sCl + TE);
    float* sM  = sRd + TE;

    int tid = threadIdx.x;
    int base = blockIdx.x * TE;
    {
        const float4* src = (const float4*)W2;
        float4* dst = (float4*)sW;
#pragma unroll
        for (int i = 0; i < 4; i++)
            dst[tid + 256 * i] = src[tid + 256 * i];
    }
    if (tid < 64) { sC[tid] = w1c[tid]; sB[tid] = b2[tid]; }
    if (tid < TE) {
        sR[tid]  = g_rowS[base + tid];
        sCl[tid] = g_colS[base + tid];
        sRd[tid] = g_radS[base + tid];
        sM[tid]  = g_mS[base + tid];
    }
    __syncthreads();

    int lane = tid & 31, wid = tid >> 5;
    float c0 = sC[lane], c1 = sC[32 + lane];

#pragma unroll 4
    for (int i = 0; i < 16; i++) {
        int el = wid * 16 + i;
        int r = sR[el], c = sCl[el];
        float rad = sRd[el];
        float v0 = silu(g_PA[r * HD + lane]      + g_PB[c * HD + lane]      + rad * c0);
        float v1 = silu(g_PA[r * HD + 32 + lane] + g_PB[c * HD + 32 + lane] + rad * c1);
        sV[el * 65 + lane]      = v0;
        sV[el * 65 + 32 + lane] = v1;
    }
    __syncthreads();

    int ge = tid >> 3, gj = tid & 7;
    int eb = ge * 4, jb = gj * 8;

    u64 acc[4][4];
    {
        U16 bb0, bb1;
        bb0.f = *(const float4*)(sB + jb);
        bb1.f = *(const float4*)(sB + jb + 4);
#pragma unroll
        for (int q = 0; q < 4; q++) {
            acc[q][0] = bb0.u[0]; acc[q][1] = bb0.u[1];
            acc[q][2] = bb1.u[0]; acc[q][3] = bb1.u[1];
        }
    }
#pragma unroll 4
    for (int k = 0; k < 64; k++) {
        U16 w0, w1;
        const float4* bp = (const float4*)(sW + k * 64 + jb);
        w0.f = bp[0]; w1.f = bp[1];
#pragma unroll
        for (int q = 0; q < 4; q++) {
            u64 a = packdup(sV[(eb + q) * 65 + k]);
            acc[q][0] = ffma2(a, w0.u[0], acc[q][0]);
            acc[q][1] = ffma2(a, w0.u[1], acc[q][1]);
            acc[q][2] = ffma2(a, w1.u[0], acc[q][2]);
            acc[q][3] = ffma2(a, w1.u[1], acc[q][3]);
        }
    }

    float run[8];
#pragma unroll
    for (int jj = 0; jj < 8; jj++) run[jj] = 0.f;
    int curR = sR[eb];
#pragma unroll
    for (int q = 0; q < 4; q++) {
        int r = sR[eb + q];
        float m = sM[eb + q];
        if (r != curR) {
            float4* b4 = (float4*)&g_agg[curR * HD + jb];
            atomicAdd(b4,     make_float4(run[0], run[1], run[2], run[3]));
            atomicAdd(b4 + 1, make_float4(run[4], run[5], run[6], run[7]));
#pragma unroll
            for (int jj = 0; jj < 8; jj++) run[jj] = 0.f;
            curR = r;
        }
#pragma unroll
        for (int jp = 0; jp < 4; jp++) {
            float2 p = unpk(acc[q][jp]);
            run[2 * jp]     += silu(p.x) * m;
            run[2 * jp + 1] += silu(p.y) * m;
        }
    }
    {
        float4* b4 = (float4*)&g_agg[curR * HD + jb];
        atomicAdd(b4,     make_float4(run[0], run[1], run[2], run[3]));
        atomicAdd(b4 + 1, make_float4(run[4], run[5], run[6], run[7]));
    }
}

// ---------------- fused node + next-layer precomp ----------------
#define NF_SMEM (8192 + 4096 + 64 * 132 + 64 * ST + 64 + 128)
__global__ __launch_bounds__(256)
void k_nodefused(const float* __restrict__ W1n,
                 const float* __restrict__ W2n,
                 const float* __restrict__ b2n,
                 const float* __restrict__ fz,
                 const float* __restrict__ Wp,
                 const float* __restrict__ bp,
                 int last) {
    extern __shared__ float sm[];
    float* sW1 = sm;
    float* sW2 = sm + 8192;
    float* sX  = sW2 + 4096;
    float* sT  = sX + 64 * 132;
    float* sB2 = sT + 64 * ST;
    float* sBp = sB2 + 64;
    float* sH  = sW1;
    float* sWp = sX;

    int tid = threadIdx.x;
    int n0 = blockIdx.x * 64;

    {
        const float4* src = (const float4*)W1n;
        float4* dst = (float4*)sW1;
#pragma unroll
        for (int i = 0; i < 8; i++)
            dst[tid + 256 * i] = src[tid + 256 * i];
    }
    {
        const float4* src = (const float4*)W2n;
        float4* dst = (float4*)sW2;
#pragma unroll
        for (int i = 0; i < 4; i++)
            dst[tid + 256 * i] = src[tid + 256 * i];
    }
    for (int idx = tid; idx < 8192; idx += 256) {
        int n = idx >> 7, c = idx & 127;
        sX[n * 132 + c] = (c < 64) ? g_h[(n0 + n) * HD + c]
                                   : g_agg[(n0 + n) * HD + (c - 64)];
    }
    for (int idx = tid; idx < 4096; idx += 256) {
        int n = idx >> 6, c = idx & 63;
        sT[n * ST + c] = fz[(n0 + n) * HD + c];
    }
    if (tid < 64) sB2[tid] = b2n[tid];
    if (tid < 128) sBp[tid] = (!last && tid < 64) ? bp[tid] : 0.f;
    __syncthreads();

    if (!last) {
        float4 z = make_float4(0.f, 0.f, 0.f, 0.f);
        float4* a4 = (float4*)&g_agg[n0 * HD];
#pragma unroll
        for (int i = 0; i < 4; i++) a4[tid + 256 * i] = z;
    }

    int gn = tid >> 4, gj = tid & 15;
    int nb = gn * 4, jb = gj * 4;

    // GEMM1: t = silu([h|agg]@W1n + FZ)
    u64 acc[4][2];
#pragma unroll
    for (int q = 0; q < 4; q++) {
        U16 f0;
        f0.f = *(const float4*)(sT + (nb + q) * ST + jb);
        acc[q][0] = f0.u[0]; acc[q][1] = f0.u[1];
    }
#pragma unroll 4
    for (int k = 0; k < 128; k++) {
        U16 w;
        w.f = *(const float4*)(sW1 + k * 64 + jb);
#pragma unroll
        for (int q = 0; q < 4; q++) {
            u64 a = packdup(sX[(nb + q) * 132 + k]);
            acc[q][0] = ffma2(a, w.u[0], acc[q][0]);
            acc[q][1] = ffma2(a, w.u[1], acc[q][1]);
        }
    }
#pragma unroll
    for (int q = 0; q < 4; q++) {
        float2 p0 = unpk(acc[q][0]);
        float2 p1 = unpk(acc[q][1]);
        float* t = sT + (nb + q) * ST + jb;
        t[0] = silu(p0.x); t[1] = silu(p0.y);
        t[2] = silu(p1.x); t[3] = silu(p1.y);
    }
    __syncthreads();

    if (!last) {
        for (int idx = tid; idx < 8192; idx += 256) {
            int k = idx >> 7, j = idx & 127;
            sWp[k * 128 + j] = (j < 64) ? Wp[k * HD + j]
                                        : Wp[(64 + k) * HD + (j - 64)];
        }
    }

    // GEMM2: h' = t@W2n + b2
    u64 acc2[4][2];
    {
        U16 b0;
        b0.f = *(const float4*)(sB2 + jb);
#pragma unroll
        for (int q = 0; q < 4; q++) { acc2[q][0] = b0.u[0]; acc2[q][1] = b0.u[1]; }
    }
#pragma unroll 4
    for (int k = 0; k < 64; k++) {
        U16 w;
        w.f = *(const float4*)(sW2 + k * 64 + jb);
#pragma unroll
        for (int q = 0; q < 4; q++) {
            u64 a = packdup(sT[(nb + q) * ST + k]);
            acc2[q][0] = ffma2(a, w.u[0], acc2[q][0]);
            acc2[q][1] = ffma2(a, w.u[1], acc2[q][1]);
        }
    }
#pragma unroll
    for (int q = 0; q < 4; q++) {
        U16 o;
        o.u[0] = acc2[q][0]; o.u[1] = acc2[q][1];
        *(float4*)&g_h[(n0 + nb + q) * HD + jb] = o.f;
        if (!last) {
            float* hrow = sH + (nb + q) * ST + jb;
            hrow[0] = o.s[0]; hrow[1] = o.s[1]; hrow[2] = o.s[2]; hrow[3] = o.s[3];
        }
    }
    if (last) return;
    __syncthreads();

    // GEMM3: [PA|PB]_{l+1} = h'@Wp + [b1p|0]
    int jb3 = gj * 8;
    u64 acc3[4][4];
    {
        U16 b0, b1v;
        b0.f  = *(const float4*)(sBp + jb3);
        b1v.f = *(const float4*)(sBp + jb3 + 4);
#pragma unroll
        for (int q = 0; q < 4; q++) {
            acc3[q][0] = b0.u[0]; acc3[q][1] = b0.u[1];
            acc3[q][2] = b1v.u[0]; acc3[q][3] = b1v.u[1];
        }
    }
#pragma unroll 4
    for (int k = 0; k < 64; k++) {
        U16 w0, w1;
        const float4* bp4 = (const float4*)(sWp + k * 128 + jb3);
        w0.f = bp4[0]; w1.f = bp4[1];
#pragma unroll
        for (int q = 0; q < 4; q++) {
            u64 a = packdup(sH[(nb + q) * ST + k]);
            acc3[q][0] = ffma2(a, w0.u[0], acc3[q][0]);
            acc3[q][1] = ffma2(a, w0.u[1], acc3[q][1]);
            acc3[q][2] = ffma2(a, w1.u[0], acc3[q][2]);
            acc3[q][3] = ffma2(a, w1.u[1], acc3[q][3]);
        }
    }
    float* dst = (gj < 8) ? g_PA : g_PB;
    int col = (gj < 8) ? jb3 : (jb3 - 64);
#pragma unroll
    for (int q = 0; q < 4; q++) {
        U16 o0, o1;
        o0.u[0] = acc3[q][0]; o0.u[1] = acc3[q][1];
        o1.u[0] = acc3[q][2]; o1.u[1] = acc3[q][3];
        float4* d4 = (float4*)&dst[(n0 + nb + q) * HD + col];
        d4[0] = o0.f; d4[1] = o1.f;
    }
}

// ---------------- zero output ----------------
__global__ void k_zero(float* __restrict__ pred) {
    pred[blockIdx.x * blockDim.x + threadIdx.x] = 0.f;
}

// ---------------- final ----------------
#define FINAL_SMEM_FLOATS (4096 * 3 + 64 * 3 + 256)
__global__ void k_final(const float* __restrict__ nmask,
                        const float* __restrict__ dw1, const float* __restrict__ db1,
                        const float* __restrict__ dw2, const float* __restrict__ db2,
                        const float* __restrict__ gw1, const float* __restrict__ gb1,
                        const float* __restrict__ gw2, const float* __restrict__ gb2,
                        const int* __restrict__ ridx, const float* __restrict__ rsign,
                        float* __restrict__ pred) {
    extern __shared__ float sm[];
    float* sD1 = sm;
    float* sD2 = sm + 4096;
    float* sG1 = sm + 8192;
    float* sDB1 = sm + 12288;
    float* sDB2 = sDB1 + 64;
    float* sGB1 = sDB2 + 64;
    float* red  = sGB1 + 64;
    int tid = threadIdx.x;
    for (int idx = tid; idx < 4096; idx += blockDim.x) {
        int k = idx >> 6, j = idx & 63;
        int si = k * 64 + ((j & 31) << 1) + (j >> 5);
        sD1[si] = dw1[k * HD + j];
        sD2[si] = dw2[k * HD + j];
        sG1[si] = gw1[k * HD + j];
    }
    if (tid < 64) { sDB1[tid] = db1[tid]; sDB2[tid] = db2[tid]; sGB1[tid] = gb1[tid]; }
    __syncthreads();
    int lane = tid & 31, wid = tid >> 5;
    int g = blockIdx.x;
    const float2* D1 = (const float2*)sD1;
    const float2* D2 = (const float2*)sD2;
    const float2* G1 = (const float2*)sG1;
    float acc0 = 0.f, acc1 = 0.f;
#pragma unroll
    for (int i = 0; i < 4; i++) {
        int n = g * NPG + wid * 4 + i;
        float hl = g_h[n * HD + lane], hh = g_h[n * HD + 32 + lane];
        float t0 = sDB1[lane], t1 = sDB1[32 + lane];
#pragma unroll
        for (int k = 0; k < 32; k++) {
            float v = __shfl_sync(0xffffffffu, hl, k);
            float2 w = D1[k * 32 + lane];
            t0 += v * w.x; t1 += v * w.y;
        }
#pragma unroll
        for (int k = 0; k < 32; k++) {
            float v = __shfl_sync(0xffffffffu, hh, k);
            float2 w = D1[(32 + k) * 32 + lane];
            t0 += v * w.x; t1 += v * w.y;
        }
        t0 = silu(t0); t1 = silu(t1);
        float o0 = sDB2[lane], o1 = sDB2[32 + lane];
#pragma unroll
        for (int k = 0; k < 32; k++) {
            float v = __shfl_sync(0xffffffffu, t0, k);
            float2 w = D2[k * 32 + lane];
            o0 += v * w.x; o1 += v * w.y;
        }
#pragma unroll
        for (int k = 0; k < 32; k++) {
            float v = __shfl_sync(0xffffffffu, t1, k);
            float2 w = D2[(32 + k) * 32 + lane];
            o0 += v * w.x; o1 += v * w.y;
        }
        float m = nmask[n];
        acc0 += o0 * m; acc1 += o1 * m;
    }
    red[wid * 64 + lane] = acc0;
    red[wid * 64 + 32 + lane] = acc1;
    __syncthreads();
    if (wid == 0) {
        float hg0 = red[lane] + red[64 + lane] + red[128 + lane] + red[192 + lane];
        float hg1 = red[32 + lane] + red[96 + lane] + red[160 + lane] + red[224 + lane];
        float t0 = sGB1[lane], t1 = sGB1[32 + lane];
#pragma unroll
        for (int k = 0; k < 32; k++) {
            float v = __shfl_sync(0xffffffffu, hg0, k);
            float2 w = G1[k * 32 + lane];
            t0 += v * w.x; t1 += v * w.y;
        }
#pragma unroll
        for (int k = 0; k < 32; k++) {
            float v = __shfl_sync(0xffffffffu, hg1, k);
            float2 w = G1[(32 + k) * 32 + lane];
            t0 += v * w.x; t1 += v * w.y;
        }
        t0 = silu(t0); t1 = silu(t1);
        float part = t0 * gw2[lane] + t1 * gw2[32 + lane];
#pragma unroll
        for (int off = 16; off > 0; off >>= 1)
            part += __shfl_xor_sync(0xffffffffu, part, off);
        if (lane == 0) {
            float val = (part + gb2[0]) * rsign[g];
            atomicAdd(&pred[ridx[g]], val);
        }
    }
}

// ---------------- launch ----------------
extern "C" void kernel_launch(void* const* d_in, const int* in_sizes, int n_in,
                              void* d_out, int out_size) {
    const float* h0    = (const float*)d_in[0];
    const float* pos   = (const float*)d_in[1];
    const int*   edges = (const int*)  d_in[2];
    const float* nmask = (const float*)d_in[3];
    const float* emask = (const float*)d_in[4];
    const int*   ridx  = (const int*)  d_in[5];
    const float* rsign = (const float*)d_in[6];
    const float* emb_w = (const float*)d_in[7];
    const float* emb_b = (const float*)d_in[8];
    const float* ew1   = (const float*)d_in[9];
    const float* eb1   = (const float*)d_in[10];
    const float* ew2   = (const float*)d_in[11];
    const float* eb2   = (const float*)d_in[12];
    const float* nw1   = (const float*)d_in[13];
    const float* nb1   = (const float*)d_in[14];
    const float* nw2   = (const float*)d_in[15];
    const float* nb2   = (const float*)d_in[16];
    const float* dw1   = (const float*)d_in[17];
    const float* db1   = (const float*)d_in[18];
    const float* dw2   = (const float*)d_in[19];
    const float* db2   = (const float*)d_in[20];
    const float* gw1   = (const float*)d_in[21];
    const float* gb1   = (const float*)d_in[22];
    const float* gw2   = (const float*)d_in[23];
    const float* gb2   = (const float*)d_in[24];
    float* pred = (float*)d_out;

    float* fzBase;
    cudaGetSymbolAddress((void**)&fzBase, g_FZ);

    cudaFuncSetAttribute(k_precomp0, cudaFuncAttributeMaxDynamicSharedMemorySize,
                         P0_SMEM * 4);
    cudaFuncSetAttribute(k_edge, cudaFuncAttributeMaxDynamicSharedMemorySize,
                         EDGE_SMEM * 4);
    cudaFuncSetAttribute(k_nodefused, cudaFuncAttributeMaxDynamicSharedMemorySize,
                         NF_SMEM * 4);
    cudaFuncSetAttribute(k_final, cudaFuncAttributeMaxDynamicSharedMemorySize,
                         FINAL_SMEM_FLOATS * 4);

    k_embed_zero<<<NND * HD / 256, 256>>>(h0, emb_w, emb_b);
    k_radial_hist<<<(NE + 255) / 256, 256>>>(edges, pos);
    k_scan<<<1, 1024>>>();
    k_precomp0<<<NND / 64, 256, P0_SMEM * 4>>>(ew1, eb1);
    k_scatterprep<<<(NE + 255) / 256, 256>>>(edges, emask);
    k_fz<<<(NL * NND * HD) / 256, 256>>>(h0, nw1, nb1);

    for (int l = 0; l < NL; l++) {
        k_edge<<<NE / TE, 256, EDGE_SMEM * 4>>>(
            ew2 + l * HD * HD, eb2 + l * HD, ew1 + l * EINC * HD + 128 * HD);
        int last = (l == NL - 1);
        k_nodefused<<<NND / 64, 256, NF_SMEM * 4>>>(
            nw1 + l * NINC * HD, nw2 + l * HD * HD, nb2 + l * HD,
            fzBase + l * NND * HD,
            last ? (const float*)0 : (ew1 + (l + 1) * EINC * HD),
            last ? (const float*)0 : (eb1 + (l + 1) * HD),
            last);
    }

    k_zero<<<NR / 256, 256>>>(pred);
    k_final<<<NG, 128, FINAL_SMEM_FLOATS * 4>>>(
        nmask, dw1, db1, dw2, db2, gw1, gb1, gw2, gb2, ridx, rsign, pred);
}